// round 1
// baseline (speedup 1.0000x reference)
#include <cuda_runtime.h>

#define BB 8
#define NX 32
#define DD 128
#define KK 256
#define HH 2
#define SROW 260   // padded smem row stride (floats): 4-bank shift per row, float4-aligned

__device__ float d_scales[4];
__device__ float d_Hbuf[3][BB][NX][KK];     // relu(x@W^T+b) for x,y,z
__device__ float d_blocksum[BB][HH][NX];    // partial exp-sums per (b,h,x)
__device__ float d_partial[BB][NX][KK];     // logits partials per (b,x)

__device__ __forceinline__ float warp_sum(float v){
#pragma unroll
  for (int o = 16; o > 0; o >>= 1) v += __shfl_xor_sync(0xffffffffu, v, o);
  return v;
}

// ---------------- K1: weight-norm scales g/||V||_F ----------------
__global__ void scale_kernel(const float* __restrict__ Vx, const float* __restrict__ Vy,
                             const float* __restrict__ Vz, const float* __restrict__ Vh,
                             const float* __restrict__ gx, const float* __restrict__ gy,
                             const float* __restrict__ gz, const float* __restrict__ gh){
  int i = blockIdx.x;
  const float* V = (i==0)?Vx:(i==1)?Vy:(i==2)?Vz:Vh;
  const float* g = (i==0)?gx:(i==1)?gy:(i==2)?gz:gh;
  int n = (i==3) ? (HH*KK) : (KK*DD);
  float s = 0.f;
  for (int j = threadIdx.x; j < n; j += blockDim.x){ float v = V[j]; s = fmaf(v, v, s); }
  __shared__ float red[8];
  s = warp_sum(s);
  if ((threadIdx.x & 31) == 0) red[threadIdx.x >> 5] = s;
  __syncthreads();
  if (threadIdx.x < 32){
    float v = (threadIdx.x < 8) ? red[threadIdx.x] : 0.f;
    v = warp_sum(v);
    if (threadIdx.x == 0) d_scales[i] = g[0] * rsqrtf(v);
  }
}

// ---------------- K2: projections _x,_y,_z = relu(in @ (s*V)^T + b) ----------------
__global__ void __launch_bounds__(256) proj_kernel(
    const float* __restrict__ x, const float* __restrict__ y, const float* __restrict__ z,
    const float* __restrict__ Vx, const float* __restrict__ Vy, const float* __restrict__ Vz,
    const float* __restrict__ bx, const float* __restrict__ by, const float* __restrict__ bz){
  int id = blockIdx.x;               // 192 blocks: b(8) x tensor(3) x rowgroup(8 of 4 rows)
  int b = id / 24; int r = id % 24; int t = r >> 3; int gq = r & 7;
  const float* in   = (t==0)?x :(t==1)?y :z;
  const float* V    = (t==0)?Vx:(t==1)?Vy:Vz;
  const float* bias = (t==0)?bx:(t==1)?by:bz;
  float scale = d_scales[t];
  __shared__ float4 srow[4][32];
  int row0 = gq * 4;
  for (int i = threadIdx.x; i < 128; i += blockDim.x){
    int rr = i >> 5, dd = i & 31;
    srow[rr][dd] = reinterpret_cast<const float4*>(in + (size_t)(b*NX + row0 + rr)*DD)[dd];
  }
  __syncthreads();
  int k = threadIdx.x;               // one output feature per thread
  const float4* Vr = reinterpret_cast<const float4*>(V + (size_t)k * DD);
  float a0 = 0.f, a1 = 0.f, a2 = 0.f, a3 = 0.f;
#pragma unroll 8
  for (int d = 0; d < 32; d++){
    float4 v  = Vr[d];
    float4 s0 = srow[0][d], s1 = srow[1][d], s2 = srow[2][d], s3 = srow[3][d];
    a0 += v.x*s0.x + v.y*s0.y + v.z*s0.z + v.w*s0.w;
    a1 += v.x*s1.x + v.y*s1.y + v.z*s1.z + v.w*s1.w;
    a2 += v.x*s2.x + v.y*s2.y + v.z*s2.z + v.w*s2.w;
    a3 += v.x*s3.x + v.y*s3.y + v.z*s3.z + v.w*s3.w;
  }
  float bk = bias[k];
  d_Hbuf[t][b][row0+0][k] = fmaxf(fmaf(a0, scale, bk), 0.f);
  d_Hbuf[t][b][row0+1][k] = fmaxf(fmaf(a1, scale, bk), 0.f);
  d_Hbuf[t][b][row0+2][k] = fmaxf(fmaf(a2, scale, bk), 0.f);
  d_Hbuf[t][b][row0+3][k] = fmaxf(fmaf(a3, scale, bk), 0.f);
}

// ---------------- K3: scores -> exp (shift=0) -> partial sums; writes e to att buffer ----------------
__global__ void __launch_bounds__(256) score_kernel(const float* __restrict__ Vh,
                                                    const float* __restrict__ bh,
                                                    float* __restrict__ gatt){
  extern __shared__ float sm[];
  float* sy   = sm;                  // 32 rows, stride SROW
  float* sz   = sm + 32*SROW;
  float* sa   = sm + 64*SROW;        // a[2][256] = _x[b,x,k] * Wh_scaled[h,k]
  float* sred = sa + 512;            // 16
  int xg = blockIdx.x, b = blockIdx.y;
  const float4* Hy4 = reinterpret_cast<const float4*>(&d_Hbuf[1][b][0][0]);
  const float4* Hz4 = reinterpret_cast<const float4*>(&d_Hbuf[2][b][0][0]);
  for (int i = threadIdx.x; i < 2048; i += 256){
    int row = i >> 6, col = i & 63;
    reinterpret_cast<float4*>(sy + row*SROW)[col] = Hy4[i];
    reinterpret_cast<float4*>(sz + row*SROW)[col] = Hz4[i];
  }
  {
    int k = threadIdx.x;
    float sh = d_scales[3];
    float xv = d_Hbuf[0][b][xg][k];
    sa[k]      = xv * sh * Vh[k];
    sa[KK + k] = xv * sh * Vh[KK + k];
  }
  __syncthreads();
  int yq = threadIdx.x >> 3, zq = threadIdx.x & 7;   // thread: 1 y, 4 z (z = zq + 8i)
  const float4* a04  = reinterpret_cast<const float4*>(sa);
  const float4* a14  = reinterpret_cast<const float4*>(sa + KK);
  const float4* yrow = reinterpret_cast<const float4*>(sy + yq*SROW);
  const float4* z0r  = reinterpret_cast<const float4*>(sz + (zq +  0)*SROW);
  const float4* z1r  = reinterpret_cast<const float4*>(sz + (zq +  8)*SROW);
  const float4* z2r  = reinterpret_cast<const float4*>(sz + (zq + 16)*SROW);
  const float4* z3r  = reinterpret_cast<const float4*>(sz + (zq + 24)*SROW);
  float acc00=0,acc01=0,acc02=0,acc03=0,acc10=0,acc11=0,acc12=0,acc13=0;
#pragma unroll 4
  for (int kb = 0; kb < 64; kb++){
    float4 a0 = a04[kb], a1 = a14[kb], yv = yrow[kb];
    float4 zv0 = z0r[kb], zv1 = z1r[kb], zv2 = z2r[kb], zv3 = z3r[kb];
#define SCOMP(c) { float p0 = a0.c*yv.c, p1 = a1.c*yv.c;                 \
    acc00 = fmaf(p0, zv0.c, acc00); acc01 = fmaf(p0, zv1.c, acc01);      \
    acc02 = fmaf(p0, zv2.c, acc02); acc03 = fmaf(p0, zv3.c, acc03);      \
    acc10 = fmaf(p1, zv0.c, acc10); acc11 = fmaf(p1, zv1.c, acc11);      \
    acc12 = fmaf(p1, zv2.c, acc12); acc13 = fmaf(p1, zv3.c, acc13); }
    SCOMP(x) SCOMP(y) SCOMP(z) SCOMP(w)
#undef SCOMP
  }
  float b0 = bh[0], b1 = bh[1];
  float e00=__expf(acc00+b0), e01=__expf(acc01+b0), e02=__expf(acc02+b0), e03=__expf(acc03+b0);
  float e10=__expf(acc10+b1), e11=__expf(acc11+b1), e12=__expf(acc12+b1), e13=__expf(acc13+b1);
  size_t base0 = ((size_t)(b*HH + 0)*NX + xg)*1024 + yq*32 + zq;
  size_t base1 = ((size_t)(b*HH + 1)*NX + xg)*1024 + yq*32 + zq;
  gatt[base0 +  0] = e00; gatt[base0 +  8] = e01; gatt[base0 + 16] = e02; gatt[base0 + 24] = e03;
  gatt[base1 +  0] = e10; gatt[base1 +  8] = e11; gatt[base1 + 16] = e12; gatt[base1 + 24] = e13;
  float ls0 = e00+e01+e02+e03, ls1 = e10+e11+e12+e13;
  ls0 = warp_sum(ls0); ls1 = warp_sum(ls1);
  int wid = threadIdx.x >> 5;
  if ((threadIdx.x & 31) == 0){ sred[wid] = ls0; sred[8 + wid] = ls1; }
  __syncthreads();
  if (threadIdx.x < 32){
    float v0 = (threadIdx.x < 8) ? sred[threadIdx.x] : 0.f;
    float v1 = (threadIdx.x < 8) ? sred[8 + threadIdx.x] : 0.f;
    v0 = warp_sum(v0); v1 = warp_sum(v1);
    if (threadIdx.x == 0){ d_blocksum[b][0][xg] = v0; d_blocksum[b][1][xg] = v1; }
  }
}

// ---------------- K4: normalize att in place + logits partials ----------------
__global__ void __launch_bounds__(256) finalize_kernel(float* __restrict__ gatt){
  extern __shared__ float sm[];
  float* sy = sm;
  float* sz = sm + 32*SROW;
  float* w  = sm + 64*SROW;          // 1024: att0+att1 for this (b,x)
  float* sx = w + 1024;              // 256
  float* sS = sx + 256;              // 2
  int xg = blockIdx.x, b = blockIdx.y;
  if (threadIdx.x < 64){
    int h = threadIdx.x >> 5, lane = threadIdx.x & 31;
    float v = d_blocksum[b][h][lane];
    v = warp_sum(v);
    if (lane == 0) sS[h] = v;
  }
  const float4* Hy4 = reinterpret_cast<const float4*>(&d_Hbuf[1][b][0][0]);
  const float4* Hz4 = reinterpret_cast<const float4*>(&d_Hbuf[2][b][0][0]);
  for (int i = threadIdx.x; i < 2048; i += 256){
    int row = i >> 6, col = i & 63;
    reinterpret_cast<float4*>(sy + row*SROW)[col] = Hy4[i];
    reinterpret_cast<float4*>(sz + row*SROW)[col] = Hz4[i];
  }
  sx[threadIdx.x] = d_Hbuf[0][b][xg][threadIdx.x];
  __syncthreads();
  float invS0 = 1.f / sS[0], invS1 = 1.f / sS[1];
  float4* g0 = reinterpret_cast<float4*>(gatt + ((size_t)(b*HH + 0)*NX + xg)*1024);
  float4* g1 = reinterpret_cast<float4*>(gatt + ((size_t)(b*HH + 1)*NX + xg)*1024);
  float4 e0 = g0[threadIdx.x], e1 = g1[threadIdx.x];
  float4 n0, n1, wv;
  n0.x = e0.x*invS0; n0.y = e0.y*invS0; n0.z = e0.z*invS0; n0.w = e0.w*invS0;
  n1.x = e1.x*invS1; n1.y = e1.y*invS1; n1.z = e1.z*invS1; n1.w = e1.w*invS1;
  wv.x = n0.x + n1.x; wv.y = n0.y + n1.y; wv.z = n0.z + n1.z; wv.w = n0.w + n1.w;
  g0[threadIdx.x] = n0; g1[threadIdx.x] = n1;
  reinterpret_cast<float4*>(w)[threadIdx.x] = wv;
  __syncthreads();
  int k = threadIdx.x;
  float zk[32];
#pragma unroll
  for (int zz = 0; zz < 32; zz++) zk[zz] = sz[zz*SROW + k];
  float v = 0.f;
#pragma unroll 4
  for (int yy = 0; yy < 32; yy++){
    const float4* wr = reinterpret_cast<const float4*>(w + yy*32);
    float t = 0.f;
#pragma unroll
    for (int zq = 0; zq < 8; zq++){
      float4 wv4 = wr[zq];
      t = fmaf(wv4.x, zk[zq*4+0], t);
      t = fmaf(wv4.y, zk[zq*4+1], t);
      t = fmaf(wv4.z, zk[zq*4+2], t);
      t = fmaf(wv4.w, zk[zq*4+3], t);
    }
    v = fmaf(sy[yy*SROW + k], t, v);
  }
  d_partial[b][xg][k] = sx[k] * v;
}

// ---------------- K5: reduce partials over x + BatchNorm(train, biased var) ----------------
__global__ void __launch_bounds__(256) bn_kernel(const float* __restrict__ gamma,
                                                 const float* __restrict__ beta,
                                                 float* __restrict__ out){
  int k = threadIdx.x;
  float l[8];
#pragma unroll
  for (int b = 0; b < 8; b++){
    float s = 0.f;
#pragma unroll
    for (int xx = 0; xx < 32; xx++) s += d_partial[b][xx][k];
    l[b] = s;
  }
  float mean = 0.f;
#pragma unroll
  for (int b = 0; b < 8; b++) mean += l[b];
  mean *= 0.125f;
  float var = 0.f;
#pragma unroll
  for (int b = 0; b < 8; b++){ float d = l[b] - mean; var = fmaf(d, d, var); }
  var *= 0.125f;
  float inv = rsqrtf(var + 1e-5f);
  float ga = gamma[k], be = beta[k];
#pragma unroll
  for (int b = 0; b < 8; b++) out[b*KK + k] = (l[b] - mean) * inv * ga + be;
}

extern "C" void kernel_launch(void* const* d_in, const int* in_sizes, int n_in,
                              void* d_out, int out_size){
  const float* x     = (const float*)d_in[0];
  const float* y     = (const float*)d_in[1];
  const float* z     = (const float*)d_in[2];
  const float* Vx    = (const float*)d_in[3];
  const float* gx    = (const float*)d_in[4];
  const float* bx    = (const float*)d_in[5];
  const float* Vy    = (const float*)d_in[6];
  const float* gy    = (const float*)d_in[7];
  const float* by    = (const float*)d_in[8];
  const float* Vz    = (const float*)d_in[9];
  const float* gz    = (const float*)d_in[10];
  const float* bz    = (const float*)d_in[11];
  const float* Vh    = (const float*)d_in[12];
  const float* gh    = (const float*)d_in[13];
  const float* bh    = (const float*)d_in[14];
  const float* gamma = (const float*)d_in[15];
  const float* beta  = (const float*)d_in[16];

  float* out = (float*)d_out;        // (out [8,256], att [8,2,32,32,32]) flattened in order
  float* att = out + BB*KK;

  const int SMEM3 = (64*SROW + 512 + 16) * (int)sizeof(float);
  const int SMEM4 = (64*SROW + 1024 + 256 + 2) * (int)sizeof(float);
  cudaFuncSetAttribute(score_kernel,    cudaFuncAttributeMaxDynamicSharedMemorySize, SMEM3);
  cudaFuncSetAttribute(finalize_kernel, cudaFuncAttributeMaxDynamicSharedMemorySize, SMEM4);

  scale_kernel<<<4, 256>>>(Vx, Vy, Vz, Vh, gx, gy, gz, gh);
  proj_kernel<<<192, 256>>>(x, y, z, Vx, Vy, Vz, bx, by, bz);
  score_kernel<<<dim3(NX, BB), 256, SMEM3>>>(Vh, bh, att);
  finalize_kernel<<<dim3(NX, BB), 256, SMEM4>>>(att);
  bn_kernel<<<1, 256>>>(gamma, beta, out);
}

// round 2
// speedup vs baseline: 1.1659x; 1.1659x over previous
#include <cuda_runtime.h>

#define BB 8
#define NX 32
#define DD 128
#define KK 256
#define HH 2
#define SROW 260   // padded smem row stride (floats) for score kernel

typedef unsigned long long ull;

__device__ float d_scales[4];
__device__ float d_Hbuf[3][BB][NX][KK];     // relu(in@W^T+b) for x,y,z
__device__ float d_blocksum[BB][HH][NX];    // partial exp-sums per (b,h,x)
__device__ float d_partial[BB][16][KK];     // logits partials per (b,x-pair)

__device__ __forceinline__ float warp_sum(float v){
#pragma unroll
  for (int o = 16; o > 0; o >>= 1) v += __shfl_xor_sync(0xffffffffu, v, o);
  return v;
}

// ---- packed f32x2 helpers ----
__device__ __forceinline__ ull pk2(float lo, float hi){
  ull r; asm("mov.b64 %0, {%1,%2};" : "=l"(r) : "f"(lo), "f"(hi)); return r;
}
__device__ __forceinline__ void fma2(ull& d, ull a, ull b){
  asm("fma.rn.f32x2 %0, %1, %2, %0;" : "+l"(d) : "l"(a), "l"(b));
}
__device__ __forceinline__ ull mul2(ull a, ull b){
  ull r; asm("mul.rn.f32x2 %0, %1, %2;" : "=l"(r) : "l"(a), "l"(b)); return r;
}
__device__ __forceinline__ ull add2(ull a, ull b){
  ull r; asm("add.rn.f32x2 %0, %1, %2;" : "=l"(r) : "l"(a), "l"(b)); return r;
}
__device__ __forceinline__ float hsum2(ull a){
  float lo, hi; asm("mov.b64 {%0,%1}, %2;" : "=f"(lo), "=f"(hi) : "l"(a)); return lo + hi;
}

// ---------------- K1: weight-norm scales g/||V||_F ----------------
__global__ void scale_kernel(const float* __restrict__ Vx, const float* __restrict__ Vy,
                             const float* __restrict__ Vz, const float* __restrict__ Vh,
                             const float* __restrict__ gx, const float* __restrict__ gy,
                             const float* __restrict__ gz, const float* __restrict__ gh){
  int i = blockIdx.x;
  const float* V = (i==0)?Vx:(i==1)?Vy:(i==2)?Vz:Vh;
  const float* g = (i==0)?gx:(i==1)?gy:(i==2)?gz:gh;
  int n = (i==3) ? (HH*KK) : (KK*DD);
  float s = 0.f;
  for (int j = threadIdx.x*4; j < n; j += blockDim.x*4){
    float4 v = reinterpret_cast<const float4*>(V)[j>>2];
    s = fmaf(v.x,v.x, fmaf(v.y,v.y, fmaf(v.z,v.z, fmaf(v.w,v.w, s))));
  }
  __shared__ float red[8];
  s = warp_sum(s);
  if ((threadIdx.x & 31) == 0) red[threadIdx.x >> 5] = s;
  __syncthreads();
  if (threadIdx.x < 32){
    float v = (threadIdx.x < 8) ? red[threadIdx.x] : 0.f;
    v = warp_sum(v);
    if (threadIdx.x == 0) d_scales[i] = g[0] * rsqrtf(v);
  }
}

// ---------------- K2: projections _x,_y,_z = relu(in @ (s*V)^T + b) ----------------
__global__ void __launch_bounds__(256) proj_kernel(
    const float* __restrict__ x, const float* __restrict__ y, const float* __restrict__ z,
    const float* __restrict__ Vx, const float* __restrict__ Vy, const float* __restrict__ Vz,
    const float* __restrict__ bx, const float* __restrict__ by, const float* __restrict__ bz){
  int id = blockIdx.x;               // 192 blocks: b(8) x tensor(3) x rowgroup(8 of 4 rows)
  int b = id / 24; int r = id % 24; int t = r >> 3; int gq = r & 7;
  const float* in   = (t==0)?x :(t==1)?y :z;
  const float* V    = (t==0)?Vx:(t==1)?Vy:Vz;
  const float* bias = (t==0)?bx:(t==1)?by:bz;
  float scale = d_scales[t];
  __shared__ float4 srow[4][32];
  int row0 = gq * 4;
  for (int i = threadIdx.x; i < 128; i += blockDim.x){
    int rr = i >> 5, dd = i & 31;
    srow[rr][dd] = reinterpret_cast<const float4*>(in + (size_t)(b*NX + row0 + rr)*DD)[dd];
  }
  __syncthreads();
  int k = threadIdx.x;
  const float4* Vr = reinterpret_cast<const float4*>(V + (size_t)k * DD);
  float a0 = 0.f, a1 = 0.f, a2 = 0.f, a3 = 0.f;
#pragma unroll 8
  for (int d = 0; d < 32; d++){
    float4 v  = Vr[d];
    float4 s0 = srow[0][d], s1 = srow[1][d], s2 = srow[2][d], s3 = srow[3][d];
    a0 += v.x*s0.x + v.y*s0.y + v.z*s0.z + v.w*s0.w;
    a1 += v.x*s1.x + v.y*s1.y + v.z*s1.z + v.w*s1.w;
    a2 += v.x*s2.x + v.y*s2.y + v.z*s2.z + v.w*s2.w;
    a3 += v.x*s3.x + v.y*s3.y + v.z*s3.z + v.w*s3.w;
  }
  float bk = bias[k];
  d_Hbuf[t][b][row0+0][k] = fmaxf(fmaf(a0, scale, bk), 0.f);
  d_Hbuf[t][b][row0+1][k] = fmaxf(fmaf(a1, scale, bk), 0.f);
  d_Hbuf[t][b][row0+2][k] = fmaxf(fmaf(a2, scale, bk), 0.f);
  d_Hbuf[t][b][row0+3][k] = fmaxf(fmaf(a3, scale, bk), 0.f);
}

// ---------------- K3: scores -> exp (shift=0) -> partial sums; 2 x per block ----------------
__global__ void __launch_bounds__(512) score_kernel(const float* __restrict__ Vh,
                                                    const float* __restrict__ bh,
                                                    float* __restrict__ gatt){
  extern __shared__ float sm[];
  float* sy   = sm;                  // 32 rows, stride SROW
  float* sz   = sm + 32*SROW;
  float* sa   = sm + 64*SROW;        // [half][h][256]
  float* sred = sa + 1024;           // 32
  int b = blockIdx.y;
  int half = threadIdx.x >> 8;
  int xg = blockIdx.x*2 + half;
  int t = threadIdx.x & 255;

  const float4* Hy4 = reinterpret_cast<const float4*>(&d_Hbuf[1][b][0][0]);
  const float4* Hz4 = reinterpret_cast<const float4*>(&d_Hbuf[2][b][0][0]);
  for (int i = threadIdx.x; i < 2048; i += 512){
    int row = i >> 6, col = i & 63;
    reinterpret_cast<float4*>(sy + row*SROW)[col] = Hy4[i];
    reinterpret_cast<float4*>(sz + row*SROW)[col] = Hz4[i];
  }
  {
    float sh = d_scales[3];
    float xv = d_Hbuf[0][b][xg][t];
    sa[half*512 + t]       = xv * sh * Vh[t];
    sa[half*512 + 256 + t] = xv * sh * Vh[KK + t];
  }
  __syncthreads();

  int yq = t >> 3, zq = t & 7;
  const float4* a04  = reinterpret_cast<const float4*>(sa + half*512);
  const float4* a14  = reinterpret_cast<const float4*>(sa + half*512 + 256);
  const float4* yrow = reinterpret_cast<const float4*>(sy + yq*SROW);
  const float4* z0r  = reinterpret_cast<const float4*>(sz + (zq +  0)*SROW);
  const float4* z1r  = reinterpret_cast<const float4*>(sz + (zq +  8)*SROW);
  const float4* z2r  = reinterpret_cast<const float4*>(sz + (zq + 16)*SROW);
  const float4* z3r  = reinterpret_cast<const float4*>(sz + (zq + 24)*SROW);

  ull A00=0ull,A01=0ull,A02=0ull,A03=0ull,A10=0ull,A11=0ull,A12=0ull,A13=0ull;
#pragma unroll 4
  for (int kb = 0; kb < 64; kb++){
    float4 a0 = a04[kb], a1 = a14[kb], yv = yrow[kb];
    float4 zv0 = z0r[kb], zv1 = z1r[kb], zv2 = z2r[kb], zv3 = z3r[kb];
    ull yp = pk2(yv.x, yv.y), yq2 = pk2(yv.z, yv.w);
    ull p0p = mul2(pk2(a0.x, a0.y), yp),  p0q = mul2(pk2(a0.z, a0.w), yq2);
    ull p1p = mul2(pk2(a1.x, a1.y), yp),  p1q = mul2(pk2(a1.z, a1.w), yq2);
    ull z0p = pk2(zv0.x, zv0.y), z0q = pk2(zv0.z, zv0.w);
    ull z1p = pk2(zv1.x, zv1.y), z1q = pk2(zv1.z, zv1.w);
    ull z2p = pk2(zv2.x, zv2.y), z2q = pk2(zv2.z, zv2.w);
    ull z3p = pk2(zv3.x, zv3.y), z3q = pk2(zv3.z, zv3.w);
    fma2(A00, p0p, z0p); fma2(A01, p0p, z1p); fma2(A02, p0p, z2p); fma2(A03, p0p, z3p);
    fma2(A10, p1p, z0p); fma2(A11, p1p, z1p); fma2(A12, p1p, z2p); fma2(A13, p1p, z3p);
    fma2(A00, p0q, z0q); fma2(A01, p0q, z1q); fma2(A02, p0q, z2q); fma2(A03, p0q, z3q);
    fma2(A10, p1q, z0q); fma2(A11, p1q, z1q); fma2(A12, p1q, z2q); fma2(A13, p1q, z3q);
  }
  float b0 = bh[0], b1 = bh[1];
  float e00=__expf(hsum2(A00)+b0), e01=__expf(hsum2(A01)+b0),
        e02=__expf(hsum2(A02)+b0), e03=__expf(hsum2(A03)+b0);
  float e10=__expf(hsum2(A10)+b1), e11=__expf(hsum2(A11)+b1),
        e12=__expf(hsum2(A12)+b1), e13=__expf(hsum2(A13)+b1);
  size_t base0 = ((size_t)(b*HH + 0)*NX + xg)*1024 + yq*32 + zq;
  size_t base1 = ((size_t)(b*HH + 1)*NX + xg)*1024 + yq*32 + zq;
  gatt[base0 +  0] = e00; gatt[base0 +  8] = e01; gatt[base0 + 16] = e02; gatt[base0 + 24] = e03;
  gatt[base1 +  0] = e10; gatt[base1 +  8] = e11; gatt[base1 + 16] = e12; gatt[base1 + 24] = e13;

  float ls0 = e00+e01+e02+e03, ls1 = e10+e11+e12+e13;
  ls0 = warp_sum(ls0); ls1 = warp_sum(ls1);
  int wid = threadIdx.x >> 5;         // 0..15 (0-7 half0, 8-15 half1)
  if ((threadIdx.x & 31) == 0){ sred[wid] = ls0; sred[16 + wid] = ls1; }
  __syncthreads();
  if (threadIdx.x < 32){
    // groups of 8: [h0,half0][h0,half1][h1,half0][h1,half1]
    float v = sred[threadIdx.x];
    v += __shfl_xor_sync(0xffffffffu, v, 1);
    v += __shfl_xor_sync(0xffffffffu, v, 2);
    v += __shfl_xor_sync(0xffffffffu, v, 4);
    if ((threadIdx.x & 7) == 0){
      int h = threadIdx.x >> 4, hf = (threadIdx.x >> 3) & 1;
      d_blocksum[b][h][blockIdx.x*2 + hf] = v;
    }
  }
}

// ---------------- K4: normalize att + logits partials; 2 x per block ----------------
__global__ void __launch_bounds__(512) finalize_kernel(float* __restrict__ gatt){
  extern __shared__ float sm[];
  float* sy = sm;            // 8192 (no pad: k is thread-contiguous)
  float* sz = sm + 8192;     // 8192
  float* w  = sm + 16384;    // 2048 (reused as vbuf at the end)
  float* sS = sm + 18432;    // 2 (+pad)
  int b = blockIdx.y, bx = blockIdx.x;
  int tid = threadIdx.x;

  if (tid < 64){
    int h = tid >> 5, lane = tid & 31;
    float v = d_blocksum[b][h][lane];
    v = warp_sum(v);
    if (lane == 0) sS[h] = 1.f / v;
  }
  const float4* Hy4 = reinterpret_cast<const float4*>(&d_Hbuf[1][b][0][0]);
  const float4* Hz4 = reinterpret_cast<const float4*>(&d_Hbuf[2][b][0][0]);
  float4* sy4 = reinterpret_cast<float4*>(sy);
  float4* sz4 = reinterpret_cast<float4*>(sz);
  for (int i = tid; i < 2048; i += 512){ sy4[i] = Hy4[i]; sz4[i] = Hz4[i]; }

  int xh = tid >> 8, k = tid & 255;
  int xg = bx*2 + xh;
  float xk = d_Hbuf[0][b][xg][k];
  __syncthreads();

  // normalize att in place + build w = att0+att1 for this thread's x
  {
    float invS0 = sS[0], invS1 = sS[1];
    float4* g0 = reinterpret_cast<float4*>(gatt + ((size_t)(b*HH + 0)*NX + xg)*1024);
    float4* g1 = reinterpret_cast<float4*>(gatt + ((size_t)(b*HH + 1)*NX + xg)*1024);
    float4 e0 = g0[k], e1 = g1[k];
    float4 n0, n1, wv;
    n0.x=e0.x*invS0; n0.y=e0.y*invS0; n0.z=e0.z*invS0; n0.w=e0.w*invS0;
    n1.x=e1.x*invS1; n1.y=e1.y*invS1; n1.z=e1.z*invS1; n1.w=e1.w*invS1;
    wv.x=n0.x+n1.x; wv.y=n0.y+n1.y; wv.z=n0.z+n1.z; wv.w=n0.w+n1.w;
    g0[k] = n0; g1[k] = n1;
    reinterpret_cast<float4*>(w + xh*1024)[k] = wv;
  }
  __syncthreads();

  // zk pairs in registers: (z,z+1) for this k
  ull zk2[16];
#pragma unroll
  for (int zp = 0; zp < 16; zp++)
    zk2[zp] = pk2(sz[(2*zp)*256 + k], sz[(2*zp+1)*256 + k]);

  float v = 0.f;
  const float* wrow = w + xh*1024;
#pragma unroll 4
  for (int yy = 0; yy < 32; yy++){
    const float4* wr = reinterpret_cast<const float4*>(wrow + yy*32);
    ull t2a = 0ull, t2b = 0ull;
#pragma unroll
    for (int q = 0; q < 8; q++){
      float4 wv = wr[q];
      fma2(t2a, pk2(wv.x, wv.y), zk2[2*q]);
      fma2(t2b, pk2(wv.z, wv.w), zk2[2*q+1]);
    }
    v = fmaf(sy[yy*256 + k], hsum2(add2(t2a, t2b)), v);
  }
  v *= xk;
  __syncthreads();
  w[tid] = v;                 // vbuf
  __syncthreads();
  if (tid < 256) d_partial[b][bx][tid] = w[tid] + w[256 + tid];
}

// ---------------- K5: reduce partials + BatchNorm(train, biased var) ----------------
__global__ void __launch_bounds__(256) bn_kernel(const float* __restrict__ gamma,
                                                 const float* __restrict__ beta,
                                                 float* __restrict__ out){
  int k = threadIdx.x;
  float l[8];
#pragma unroll
  for (int b = 0; b < 8; b++){
    float s = 0.f;
#pragma unroll
    for (int xx = 0; xx < 16; xx++) s += d_partial[b][xx][k];
    l[b] = s;
  }
  float mean = 0.f;
#pragma unroll
  for (int b = 0; b < 8; b++) mean += l[b];
  mean *= 0.125f;
  float var = 0.f;
#pragma unroll
  for (int b = 0; b < 8; b++){ float d = l[b] - mean; var = fmaf(d, d, var); }
  var *= 0.125f;
  float inv = rsqrtf(var + 1e-5f);
  float ga = gamma[k], be = beta[k];
#pragma unroll
  for (int b = 0; b < 8; b++) out[b*KK + k] = (l[b] - mean) * inv * ga + be;
}

extern "C" void kernel_launch(void* const* d_in, const int* in_sizes, int n_in,
                              void* d_out, int out_size){
  const float* x     = (const float*)d_in[0];
  const float* y     = (const float*)d_in[1];
  const float* z     = (const float*)d_in[2];
  const float* Vx    = (const float*)d_in[3];
  const float* gx    = (const float*)d_in[4];
  const float* bx    = (const float*)d_in[5];
  const float* Vy    = (const float*)d_in[6];
  const float* gy    = (const float*)d_in[7];
  const float* by    = (const float*)d_in[8];
  const float* Vz    = (const float*)d_in[9];
  const float* gz    = (const float*)d_in[10];
  const float* bz    = (const float*)d_in[11];
  const float* Vh    = (const float*)d_in[12];
  const float* gh    = (const float*)d_in[13];
  const float* bh    = (const float*)d_in[14];
  const float* gamma = (const float*)d_in[15];
  const float* beta  = (const float*)d_in[16];

  float* out = (float*)d_out;        // (out [8,256], att [8,2,32,32,32]) flattened in order
  float* att = out + BB*KK;

  const int SMEM3 = (64*SROW + 1024 + 32) * (int)sizeof(float);
  const int SMEM4 = (8192 + 8192 + 2048 + 8) * (int)sizeof(float);
  cudaFuncSetAttribute(score_kernel,    cudaFuncAttributeMaxDynamicSharedMemorySize, SMEM3);
  cudaFuncSetAttribute(finalize_kernel, cudaFuncAttributeMaxDynamicSharedMemorySize, SMEM4);

  scale_kernel<<<4, 256>>>(Vx, Vy, Vz, Vh, gx, gy, gz, gh);
  proj_kernel<<<192, 256>>>(x, y, z, Vx, Vy, Vz, bx, by, bz);
  score_kernel<<<dim3(16, BB), 512, SMEM3>>>(Vh, bh, att);
  finalize_kernel<<<dim3(16, BB), 512, SMEM4>>>(att);
  bn_kernel<<<1, 256>>>(gamma, beta, out);
}